// round 14
// baseline (speedup 1.0000x reference)
#include <cuda_runtime.h>
#include <cuda_fp16.h>
#include <stdint.h>
#include <math.h>

#define B_ 16
#define N_ 2048
#define C_ 512
#define D_ 64
#define NT (N_ / 64)

__device__ __half g_Qh[B_ * N_ * D_];
__device__ __half g_Kh[B_ * N_ * D_];
__device__ __half g_Vt[B_ * C_ * N_];   // transposed: [b][c][n]
__device__ __half g_Xh[B_ * N_ * C_];
__device__ __half g_Wqh[D_ * C_];
__device__ __half g_Wkh[D_ * C_];
__device__ __half g_Wvh[C_ * C_];

// ---- fp16 mma m16n8k16, f32 accum ----
__device__ __forceinline__ void mma_f16(float c[4], unsigned a0, unsigned a1,
                                        unsigned a2, unsigned a3,
                                        unsigned b0, unsigned b1)
{
    asm volatile(
        "mma.sync.aligned.m16n8k16.row.col.f32.f16.f16.f32 "
        "{%0,%1,%2,%3}, {%4,%5,%6,%7}, {%8,%9}, {%0,%1,%2,%3};\n"
        : "+f"(c[0]), "+f"(c[1]), "+f"(c[2]), "+f"(c[3])
        : "r"(a0), "r"(a1), "r"(a2), "r"(a3), "r"(b0), "r"(b1));
}
__device__ __forceinline__ void ldsm4(unsigned& r0, unsigned& r1,
                                      unsigned& r2, unsigned& r3, uint32_t a)
{
    asm volatile("ldmatrix.sync.aligned.m8n8.x4.shared.b16 {%0,%1,%2,%3}, [%4];\n"
                 : "=r"(r0), "=r"(r1), "=r"(r2), "=r"(r3) : "r"(a));
}
__device__ __forceinline__ void cpa16(uint32_t dst, const void* src)
{
    asm volatile("cp.async.cg.shared.global [%0], [%1], 16;\n"
                 :: "r"(dst), "l"(src));
}
#define CP_COMMIT() asm volatile("cp.async.commit_group;\n" ::)
#define CP_WAIT(n)  asm volatile("cp.async.wait_group %0;\n" :: "n"(n))

// pack two (s-mx)*log2e values and take 2^x in one f16x2 MUFU op
__device__ __forceinline__ unsigned exp2_h2(float d0, float d1)
{
    __half2 hd = __floats2half2_rn(d0, d1);
    unsigned e;
    asm("ex2.approx.f16x2 %0, %1;" : "=r"(e) : "r"(*(unsigned*)&hd));
    return e;
}

// ---------------------------------------------------------------------------
// f32 -> f16 convert (vectorized, n % 8 == 0)
// ---------------------------------------------------------------------------
__global__ void f2h_kernel(const float* __restrict__ in, __half* __restrict__ out,
                           int n)
{
    int i = (blockIdx.x * blockDim.x + threadIdx.x) * 8;
    if (i < n) {
        float4 v0 = *(const float4*)(in + i);
        float4 v1 = *(const float4*)(in + i + 4);
        __half2 h[4];
        h[0] = __floats2half2_rn(v0.x, v0.y);
        h[1] = __floats2half2_rn(v0.z, v0.w);
        h[2] = __floats2half2_rn(v1.x, v1.y);
        h[3] = __floats2half2_rn(v1.z, v1.w);
        *(uint4*)(out + i) = *(uint4*)h;
    }
}

// ---------------------------------------------------------------------------
// Fused fp16 projection: out[m,o] = sum_c Xh[m,c]*Wh[o,c] + bias[o]
// blockIdx.x: 0 -> Qh, 1 -> Kh, 2..9 -> Vt slice. 256 threads, double-buffered.
// ---------------------------------------------------------------------------
__global__ __launch_bounds__(256) void proj_kernel(
    const float* __restrict__ bq, const float* __restrict__ bk,
    const float* __restrict__ bv)
{
    __shared__ __half Ps[4 * 64 * 72];   // Xs[2], Ws[2]
    const uint32_t smem_u32 = (uint32_t)__cvta_generic_to_shared(Ps);
#define XS_OFF(s) ((s) * 4608)
#define WS_OFF(s) (9216 + (s) * 4608)

    const int tid = threadIdx.x;
    const int warp = tid >> 5, lane = tid & 31;
    const int g = lane >> 2, t = lane & 3;
    const int m0 = blockIdx.y * 64;
    const int wm = (warp >> 1) * 16;
    const int wn = (warp & 1) * 32;
    const int lm_row = lane & 15, lm_k = 8 * (lane >> 4);

    const __half* Wp; const float* biasp; int o0;
    if (blockIdx.x == 0)      { Wp = g_Wqh; biasp = bq; o0 = 0; }
    else if (blockIdx.x == 1) { Wp = g_Wkh; biasp = bk; o0 = 0; }
    else { o0 = (blockIdx.x - 2) * 64; Wp = g_Wvh + (size_t)o0 * C_; biasp = bv + o0; }

    const __half* Xg = g_Xh + (size_t)m0 * C_;

    float acc[4][4];
#pragma unroll
    for (int j = 0; j < 4; j++)
#pragma unroll
        for (int i = 0; i < 4; i++) acc[j][i] = 0.f;

    // prologue: stage 0 (k-chunk 0)
    {
#pragma unroll
        for (int l = 0; l < 2; l++) {
            int f = tid + l * 256;
            int row = f >> 3, c8 = (f & 7) * 8;
            cpa16(smem_u32 + (XS_OFF(0) + row * 72 + c8) * 2, Xg + (size_t)row * C_ + c8);
            cpa16(smem_u32 + (WS_OFF(0) + row * 72 + c8) * 2, Wp + (size_t)row * C_ + c8);
        }
        CP_COMMIT();
    }

    for (int kc = 0; kc < 8; kc++) {
        __syncthreads();
        if (kc + 1 < 8) {
            int s = (kc + 1) & 1, kt = (kc + 1) * 64;
#pragma unroll
            for (int l = 0; l < 2; l++) {
                int f = tid + l * 256;
                int row = f >> 3, c8 = (f & 7) * 8;
                cpa16(smem_u32 + (XS_OFF(s) + row * 72 + c8) * 2,
                      Xg + (size_t)row * C_ + kt + c8);
                cpa16(smem_u32 + (WS_OFF(s) + row * 72 + c8) * 2,
                      Wp + (size_t)row * C_ + kt + c8);
            }
            CP_COMMIT();
            CP_WAIT(1);
        } else {
            CP_WAIT(0);
        }
        __syncthreads();

        const int s = kc & 1;
        const uint32_t xs = smem_u32 + XS_OFF(s) * 2;
        const uint32_t ws = smem_u32 + WS_OFF(s) * 2;
#pragma unroll
        for (int kk = 0; kk < 4; kk++) {
            int k0 = kk * 16;
            unsigned a0, a1, a2, a3;
            ldsm4(a0, a1, a2, a3, xs + ((wm + lm_row) * 72 + k0 + lm_k) * 2);
#pragma unroll
            for (int jj = 0; jj < 2; jj++) {
                unsigned r0, r1, r2, r3;
                ldsm4(r0, r1, r2, r3,
                      ws + ((wn + 16 * jj + lm_row) * 72 + k0 + lm_k) * 2);
                mma_f16(acc[2 * jj],     a0, a1, a2, a3, r0, r2);
                mma_f16(acc[2 * jj + 1], a0, a1, a2, a3, r1, r3);
            }
        }
    }

    if (blockIdx.x < 2) {
        __half* outh = (blockIdx.x == 0) ? g_Qh : g_Kh;
#pragma unroll
        for (int j = 0; j < 4; j++) {
            int col = wn + 8 * j + 2 * t;
            float bv0 = biasp[col], bv1 = biasp[col + 1];
            __half2 h0 = __floats2half2_rn(acc[j][0] + bv0, acc[j][1] + bv1);
            __half2 h1 = __floats2half2_rn(acc[j][2] + bv0, acc[j][3] + bv1);
            *(__half2*)(outh + (size_t)(m0 + wm + g) * D_ + col) = h0;
            *(__half2*)(outh + (size_t)(m0 + wm + 8 + g) * D_ + col) = h1;
        }
    } else {
        int bb = m0 >> 11;
        int nn = m0 & (N_ - 1);
#pragma unroll
        for (int j = 0; j < 4; j++) {
            int col = wn + 8 * j + 2 * t;
            float bv0 = biasp[col], bv1 = biasp[col + 1];
            size_t c0b = ((size_t)bb * C_ + o0 + col) * N_;
            size_t c1b = c0b + N_;
            g_Vt[c0b + nn + wm + g]     = __float2half(acc[j][0] + bv0);
            g_Vt[c1b + nn + wm + g]     = __float2half(acc[j][1] + bv1);
            g_Vt[c0b + nn + wm + 8 + g] = __float2half(acc[j][2] + bv0);
            g_Vt[c1b + nn + wm + 8 + g] = __float2half(acc[j][3] + bv1);
        }
    }
#undef XS_OFF
#undef WS_OFF
}

// ---------------------------------------------------------------------------
// Flash attention: fp16 mma, ldmatrix, cp.async double-buffered K/V,
// f16x2 ex2 softmax, skip-rescale fast path.
// Grid (cs=4 x qt=32 x b=16), 128 threads (4 warps). Warp w: q-rows [16w,16w+16).
// ---------------------------------------------------------------------------
__global__ __launch_bounds__(128, 3) void attn_kernel(
    const float* __restrict__ x, const float* __restrict__ gamma_p,
    float* __restrict__ out)
{
    extern __shared__ __half smh[];
    const uint32_t smem_u32 = (uint32_t)__cvta_generic_to_shared(smh);
#define KS_OFF(s) (4608 + (s) * 4608)
#define VS_OFF(s) (13824 + (s) * 9216)

    const int tid = threadIdx.x;
    const int warp = tid >> 5, lane = tid & 31;
    const int g = lane >> 2, t = lane & 3;
    const int cs = blockIdx.x, qt = blockIdx.y, b = blockIdx.z;
    const int wm = warp * 16;
    const int lm_row = lane & 15, lm_k = 8 * (lane >> 4);
    const float LOG2E = 1.44269504f;

    const __half* Qg = g_Qh + ((size_t)b * N_ + qt * 64) * D_;
    const __half* Kg = g_Kh + (size_t)b * N_ * D_;
    const __half* Vg = g_Vt + ((size_t)b * C_ + cs * 128) * N_;

    // prologue: Q tile + K/V stage 0, one cp.async group
    {
#pragma unroll
        for (int l = 0; l < 4; l++) {
            int f = tid + l * 128;
            int row = f >> 3, c8 = (f & 7) * 8;
            cpa16(smem_u32 + (row * 72 + c8) * 2, Qg + (size_t)row * D_ + c8);
            cpa16(smem_u32 + (KS_OFF(0) + row * 72 + c8) * 2,
                  Kg + (size_t)row * D_ + c8);
        }
#pragma unroll
        for (int l = 0; l < 8; l++) {
            int f = tid + l * 128;
            int row = f >> 3, c8 = (f & 7) * 8;
            cpa16(smem_u32 + (VS_OFF(0) + row * 72 + c8) * 2,
                  Vg + (size_t)row * N_ + c8);
        }
        CP_COMMIT();
    }

    float m0r = -INFINITY, m1r = -INFINITY, l0r = 0.f, l1r = 0.f;
    float acc[16][4];
#pragma unroll
    for (int j = 0; j < 16; j++)
#pragma unroll
        for (int i = 0; i < 4; i++) acc[j][i] = 0.f;

    for (int mt = 0; mt < NT; mt++) {
        __syncthreads();   // protect stage being overwritten below
        if (mt + 1 < NT) {
            int s = (mt + 1) & 1, n0g = (mt + 1) * 64;
#pragma unroll
            for (int l = 0; l < 4; l++) {
                int f = tid + l * 128;
                int row = f >> 3, c8 = (f & 7) * 8;
                cpa16(smem_u32 + (KS_OFF(s) + row * 72 + c8) * 2,
                      Kg + (size_t)(n0g + row) * D_ + c8);
            }
#pragma unroll
            for (int l = 0; l < 8; l++) {
                int f = tid + l * 128;
                int row = f >> 3, c8 = (f & 7) * 8;
                cpa16(smem_u32 + (VS_OFF(s) + row * 72 + c8) * 2,
                      Vg + (size_t)row * N_ + n0g + c8);
            }
            CP_COMMIT();
            CP_WAIT(1);
        } else {
            CP_WAIT(0);
        }
        __syncthreads();

        const int s = mt & 1;
        const uint32_t ks = smem_u32 + KS_OFF(s) * 2;
        const uint32_t vs = smem_u32 + VS_OFF(s) * 2;

        // ---- S = Q * K^T : warp tile 16 x 64 ----
        float sc[8][4];
#pragma unroll
        for (int j = 0; j < 8; j++)
#pragma unroll
            for (int i = 0; i < 4; i++) sc[j][i] = 0.f;
#pragma unroll
        for (int kk = 0; kk < 4; kk++) {
            int k0 = kk * 16;
            unsigned a0, a1, a2, a3;
            ldsm4(a0, a1, a2, a3,
                  smem_u32 + ((wm + lm_row) * 72 + k0 + lm_k) * 2);
#pragma unroll
            for (int jj = 0; jj < 4; jj++) {
                unsigned r0, r1, r2, r3;
                ldsm4(r0, r1, r2, r3, ks + ((16 * jj + lm_row) * 72 + k0 + lm_k) * 2);
                mma_f16(sc[2 * jj],     a0, a1, a2, a3, r0, r2);
                mma_f16(sc[2 * jj + 1], a0, a1, a2, a3, r1, r3);
            }
        }

        // ---- online softmax (registers, f16x2 ex2) ----
        float mx0 = m0r, mx1 = m1r;
#pragma unroll
        for (int j = 0; j < 8; j++) {
            mx0 = fmaxf(mx0, fmaxf(sc[j][0], sc[j][1]));
            mx1 = fmaxf(mx1, fmaxf(sc[j][2], sc[j][3]));
        }
        mx0 = fmaxf(mx0, __shfl_xor_sync(0xffffffffu, mx0, 1));
        mx0 = fmaxf(mx0, __shfl_xor_sync(0xffffffffu, mx0, 2));
        mx1 = fmaxf(mx1, __shfl_xor_sync(0xffffffffu, mx1, 1));
        mx1 = fmaxf(mx1, __shfl_xor_sync(0xffffffffu, mx1, 2));

        float sum0 = 0.f, sum1 = 0.f;
        unsigned ph0[8], ph1[8];
#pragma unroll
        for (int j = 0; j < 8; j++) {
            unsigned e0 = exp2_h2((sc[j][0] - mx0) * LOG2E,
                                  (sc[j][1] - mx0) * LOG2E);
            unsigned e1 = exp2_h2((sc[j][2] - mx1) * LOG2E,
                                  (sc[j][3] - mx1) * LOG2E);
            ph0[j] = e0; ph1[j] = e1;
            float2 f0 = __half22float2(*(__half2*)&e0);
            float2 f1 = __half22float2(*(__half2*)&e1);
            sum0 += f0.x + f0.y;
            sum1 += f1.x + f1.y;
        }
        sum0 += __shfl_xor_sync(0xffffffffu, sum0, 1);
        sum0 += __shfl_xor_sync(0xffffffffu, sum0, 2);
        sum1 += __shfl_xor_sync(0xffffffffu, sum1, 1);
        sum1 += __shfl_xor_sync(0xffffffffu, sum1, 2);

        // skip-rescale fast path: common once running max stabilizes
        if (mx0 == m0r && mx1 == m1r) {
            l0r += sum0;
            l1r += sum1;
        } else {
            float scl0 = __expf(m0r - mx0);
            float scl1 = __expf(m1r - mx1);
            l0r = l0r * scl0 + sum0;
            l1r = l1r * scl1 + sum1;
            m0r = mx0; m1r = mx1;
#pragma unroll
            for (int j = 0; j < 16; j++) {
                acc[j][0] *= scl0; acc[j][1] *= scl0;
                acc[j][2] *= scl1; acc[j][3] *= scl1;
            }
        }

        // ---- O += P * V : warp tile 16 x 128, P from registers ----
#pragma unroll
        for (int kk = 0; kk < 4; kk++) {
            int k0 = kk * 16;
            unsigned a0 = ph0[2 * kk],     a1 = ph1[2 * kk];
            unsigned a2 = ph0[2 * kk + 1], a3 = ph1[2 * kk + 1];
#pragma unroll
            for (int jj = 0; jj < 8; jj++) {
                unsigned r0, r1, r2, r3;
                ldsm4(r0, r1, r2, r3, vs + ((16 * jj + lm_row) * 72 + k0 + lm_k) * 2);
                mma_f16(acc[2 * jj],     a0, a1, a2, a3, r0, r2);
                mma_f16(acc[2 * jj + 1], a0, a1, a2, a3, r1, r3);
            }
        }
    }

    // ---- epilogue: out = gamma * (O / l) + x ----
    const float ga = gamma_p[0];
    const float inv0 = 1.f / l0r, inv1 = 1.f / l1r;
    size_t base0 = ((size_t)b * N_ + qt * 64 + wm + g) * C_ + cs * 128;
    size_t base1 = base0 + (size_t)8 * C_;
#pragma unroll
    for (int j = 0; j < 16; j++) {
        int col = 8 * j + 2 * t;
        float2 x0 = *(const float2*)(x + base0 + col);
        float2 x1 = *(const float2*)(x + base1 + col);
        float2 o0, o1;
        o0.x = ga * acc[j][0] * inv0 + x0.x;
        o0.y = ga * acc[j][1] * inv0 + x0.y;
        o1.x = ga * acc[j][2] * inv1 + x1.x;
        o1.y = ga * acc[j][3] * inv1 + x1.y;
        *(float2*)(out + base0 + col) = o0;
        *(float2*)(out + base1 + col) = o1;
    }
#undef KS_OFF
#undef VS_OFF
}

// ---------------------------------------------------------------------------
extern "C" void kernel_launch(void* const* d_in, const int* in_sizes, int n_in,
                              void* d_out, int out_size)
{
    const float* x     = (const float*)d_in[0];
    const float* Wq    = (const float*)d_in[1];
    const float* bq    = (const float*)d_in[2];
    const float* Wk    = (const float*)d_in[3];
    const float* bk    = (const float*)d_in[4];
    const float* Wv    = (const float*)d_in[5];
    const float* bv    = (const float*)d_in[6];
    const float* gamma = (const float*)d_in[7];
    float* out = (float*)d_out;

    __half *xh, *wqh, *wkh, *wvh;
    cudaGetSymbolAddress((void**)&xh,  g_Xh);
    cudaGetSymbolAddress((void**)&wqh, g_Wqh);
    cudaGetSymbolAddress((void**)&wkh, g_Wkh);
    cudaGetSymbolAddress((void**)&wvh, g_Wvh);

    const int nx = B_ * N_ * C_;
    f2h_kernel<<<nx / (256 * 8), 256>>>(x, xh, nx);
    f2h_kernel<<<(D_ * C_) / (256 * 8), 256>>>(Wq, wqh, D_ * C_);
    f2h_kernel<<<(D_ * C_) / (256 * 8), 256>>>(Wk, wkh, D_ * C_);
    f2h_kernel<<<(C_ * C_) / (256 * 8), 256>>>(Wv, wvh, C_ * C_);

    proj_kernel<<<dim3(10, (B_ * N_) / 64), 256>>>(bq, bk, bv);

    const int smem_bytes = 32256 * 2;   // 64512
    cudaFuncSetAttribute(attn_kernel,
                         cudaFuncAttributeMaxDynamicSharedMemorySize, smem_bytes);
    attn_kernel<<<dim3(C_ / 128, N_ / 64, B_), 128, smem_bytes>>>(x, gamma, out);
}

// round 16
// speedup vs baseline: 1.1083x; 1.1083x over previous
#include <cuda_runtime.h>
#include <cuda_fp16.h>
#include <stdint.h>
#include <math.h>

#define B_ 16
#define N_ 2048
#define C_ 512
#define D_ 64
#define NT (N_ / 64)
#define CS_ 2           // channel slices
#define CH_ 256         // channels per block

__device__ __half g_Qh[B_ * N_ * D_];
__device__ __half g_Kh[B_ * N_ * D_];
__device__ __half g_Vt[B_ * C_ * N_];   // transposed: [b][c][n]
__device__ __half g_Xh[B_ * N_ * C_];
__device__ __half g_Wqh[D_ * C_];
__device__ __half g_Wkh[D_ * C_];
__device__ __half g_Wvh[C_ * C_];

// ---- fp16 mma m16n8k16, f32 accum ----
__device__ __forceinline__ void mma_f16(float c[4], unsigned a0, unsigned a1,
                                        unsigned a2, unsigned a3,
                                        unsigned b0, unsigned b1)
{
    asm volatile(
        "mma.sync.aligned.m16n8k16.row.col.f32.f16.f16.f32 "
        "{%0,%1,%2,%3}, {%4,%5,%6,%7}, {%8,%9}, {%0,%1,%2,%3};\n"
        : "+f"(c[0]), "+f"(c[1]), "+f"(c[2]), "+f"(c[3])
        : "r"(a0), "r"(a1), "r"(a2), "r"(a3), "r"(b0), "r"(b1));
}
__device__ __forceinline__ void ldsm4(unsigned& r0, unsigned& r1,
                                      unsigned& r2, unsigned& r3, uint32_t a)
{
    asm volatile("ldmatrix.sync.aligned.m8n8.x4.shared.b16 {%0,%1,%2,%3}, [%4];\n"
                 : "=r"(r0), "=r"(r1), "=r"(r2), "=r"(r3) : "r"(a));
}
__device__ __forceinline__ void cpa16(uint32_t dst, const void* src)
{
    asm volatile("cp.async.cg.shared.global [%0], [%1], 16;\n"
                 :: "r"(dst), "l"(src));
}
#define CP_COMMIT() asm volatile("cp.async.commit_group;\n" ::)
#define CP_WAIT(n)  asm volatile("cp.async.wait_group %0;\n" :: "n"(n))
__device__ __forceinline__ unsigned pack_h2(float lo, float hi) {
    __half2 h = __floats2half2_rn(lo, hi);
    return *(unsigned*)&h;
}

// ---------------------------------------------------------------------------
// f32 -> f16 convert (vectorized, n % 8 == 0)
// ---------------------------------------------------------------------------
__global__ void f2h_kernel(const float* __restrict__ in, __half* __restrict__ out,
                           int n)
{
    int i = (blockIdx.x * blockDim.x + threadIdx.x) * 8;
    if (i < n) {
        float4 v0 = *(const float4*)(in + i);
        float4 v1 = *(const float4*)(in + i + 4);
        __half2 h[4];
        h[0] = __floats2half2_rn(v0.x, v0.y);
        h[1] = __floats2half2_rn(v0.z, v0.w);
        h[2] = __floats2half2_rn(v1.x, v1.y);
        h[3] = __floats2half2_rn(v1.z, v1.w);
        *(uint4*)(out + i) = *(uint4*)h;
    }
}

// ---------------------------------------------------------------------------
// Fused fp16 projection: out[m,o] = sum_c Xh[m,c]*Wh[o,c] + bias[o]
// blockIdx.x: 0 -> Qh, 1 -> Kh, 2..9 -> Vt slice. 256 threads, double-buffered.
// ---------------------------------------------------------------------------
__global__ __launch_bounds__(256) void proj_kernel(
    const float* __restrict__ bq, const float* __restrict__ bk,
    const float* __restrict__ bv)
{
    __shared__ __half Ps[4 * 64 * 72];   // Xs[2], Ws[2]
    const uint32_t smem_u32 = (uint32_t)__cvta_generic_to_shared(Ps);
#define XS_OFF(s) ((s) * 4608)
#define WS_OFF(s) (9216 + (s) * 4608)

    const int tid = threadIdx.x;
    const int warp = tid >> 5, lane = tid & 31;
    const int g = lane >> 2, t = lane & 3;
    const int m0 = blockIdx.y * 64;
    const int wm = (warp >> 1) * 16;
    const int wn = (warp & 1) * 32;
    const int lm_row = lane & 15, lm_k = 8 * (lane >> 4);

    const __half* Wp; const float* biasp; int o0;
    if (blockIdx.x == 0)      { Wp = g_Wqh; biasp = bq; o0 = 0; }
    else if (blockIdx.x == 1) { Wp = g_Wkh; biasp = bk; o0 = 0; }
    else { o0 = (blockIdx.x - 2) * 64; Wp = g_Wvh + (size_t)o0 * C_; biasp = bv + o0; }

    const __half* Xg = g_Xh + (size_t)m0 * C_;

    float acc[4][4];
#pragma unroll
    for (int j = 0; j < 4; j++)
#pragma unroll
        for (int i = 0; i < 4; i++) acc[j][i] = 0.f;

    // prologue: stage 0 (k-chunk 0)
    {
#pragma unroll
        for (int l = 0; l < 2; l++) {
            int f = tid + l * 256;
            int row = f >> 3, c8 = (f & 7) * 8;
            cpa16(smem_u32 + (XS_OFF(0) + row * 72 + c8) * 2, Xg + (size_t)row * C_ + c8);
            cpa16(smem_u32 + (WS_OFF(0) + row * 72 + c8) * 2, Wp + (size_t)row * C_ + c8);
        }
        CP_COMMIT();
    }

    for (int kc = 0; kc < 8; kc++) {
        __syncthreads();
        if (kc + 1 < 8) {
            int s = (kc + 1) & 1, kt = (kc + 1) * 64;
#pragma unroll
            for (int l = 0; l < 2; l++) {
                int f = tid + l * 256;
                int row = f >> 3, c8 = (f & 7) * 8;
                cpa16(smem_u32 + (XS_OFF(s) + row * 72 + c8) * 2,
                      Xg + (size_t)row * C_ + kt + c8);
                cpa16(smem_u32 + (WS_OFF(s) + row * 72 + c8) * 2,
                      Wp + (size_t)row * C_ + kt + c8);
            }
            CP_COMMIT();
            CP_WAIT(1);
        } else {
            CP_WAIT(0);
        }
        __syncthreads();

        const int s = kc & 1;
        const uint32_t xs = smem_u32 + XS_OFF(s) * 2;
        const uint32_t ws = smem_u32 + WS_OFF(s) * 2;
#pragma unroll
        for (int kk = 0; kk < 4; kk++) {
            int k0 = kk * 16;
            unsigned a0, a1, a2, a3;
            ldsm4(a0, a1, a2, a3, xs + ((wm + lm_row) * 72 + k0 + lm_k) * 2);
#pragma unroll
            for (int jj = 0; jj < 2; jj++) {
                unsigned r0, r1, r2, r3;
                ldsm4(r0, r1, r2, r3,
                      ws + ((wn + 16 * jj + lm_row) * 72 + k0 + lm_k) * 2);
                mma_f16(acc[2 * jj],     a0, a1, a2, a3, r0, r2);
                mma_f16(acc[2 * jj + 1], a0, a1, a2, a3, r1, r3);
            }
        }
    }

    if (blockIdx.x < 2) {
        __half* outh = (blockIdx.x == 0) ? g_Qh : g_Kh;
#pragma unroll
        for (int j = 0; j < 4; j++) {
            int col = wn + 8 * j + 2 * t;
            float bv0 = biasp[col], bv1 = biasp[col + 1];
            __half2 h0 = __floats2half2_rn(acc[j][0] + bv0, acc[j][1] + bv1);
            __half2 h1 = __floats2half2_rn(acc[j][2] + bv0, acc[j][3] + bv1);
            *(__half2*)(outh + (size_t)(m0 + wm + g) * D_ + col) = h0;
            *(__half2*)(outh + (size_t)(m0 + wm + 8 + g) * D_ + col) = h1;
        }
    } else {
        int bb = m0 >> 11;
        int nn = m0 & (N_ - 1);
#pragma unroll
        for (int j = 0; j < 4; j++) {
            int col = wn + 8 * j + 2 * t;
            float bv0 = biasp[col], bv1 = biasp[col + 1];
            size_t c0b = ((size_t)bb * C_ + o0 + col) * N_;
            size_t c1b = c0b + N_;
            g_Vt[c0b + nn + wm + g]     = __float2half(acc[j][0] + bv0);
            g_Vt[c1b + nn + wm + g]     = __float2half(acc[j][1] + bv1);
            g_Vt[c0b + nn + wm + 8 + g] = __float2half(acc[j][2] + bv0);
            g_Vt[c1b + nn + wm + 8 + g] = __float2half(acc[j][3] + bv1);
        }
    }
#undef XS_OFF
#undef WS_OFF
}

// ---------------------------------------------------------------------------
// Flash attention, cs=2: each block owns 256 V-channels (S computed 2x total,
// not 4x). fp16 mma, ldmatrix, cp.async double-buffered K/V.
// Grid (cs=2 x qt=32 x b=16), 128 threads (4 warps). Warp w: q-rows [16w,16w+16),
// full 64-key S band, PV tile 16x256 (acc[32][4]).
// smem (halves): Qs @0 (64*72), Ks[s] @4608+s*4608, Vs[s] @13824+s*18432.
// ---------------------------------------------------------------------------
__global__ __launch_bounds__(128, 2) void attn_kernel(
    const float* __restrict__ x, const float* __restrict__ gamma_p,
    float* __restrict__ out)
{
    extern __shared__ __half smh[];
    const uint32_t smem_u32 = (uint32_t)__cvta_generic_to_shared(smh);
#define KS_OFF(s) (4608 + (s) * 4608)
#define VS_OFF(s) (13824 + (s) * 18432)

    const int tid = threadIdx.x;
    const int warp = tid >> 5, lane = tid & 31;
    const int g = lane >> 2, t = lane & 3;
    const int cs = blockIdx.x, qt = blockIdx.y, b = blockIdx.z;
    const int wm = warp * 16;
    const int lm_row = lane & 15, lm_k = 8 * (lane >> 4);

    const __half* Qg = g_Qh + ((size_t)b * N_ + qt * 64) * D_;
    const __half* Kg = g_Kh + (size_t)b * N_ * D_;
    const __half* Vg = g_Vt + ((size_t)b * C_ + cs * CH_) * N_;

    // prologue: Q tile + K/V stage 0, one cp.async group
    {
#pragma unroll
        for (int l = 0; l < 4; l++) {
            int f = tid + l * 128;
            int row = f >> 3, c8 = (f & 7) * 8;
            cpa16(smem_u32 + (row * 72 + c8) * 2, Qg + (size_t)row * D_ + c8);
            cpa16(smem_u32 + (KS_OFF(0) + row * 72 + c8) * 2,
                  Kg + (size_t)row * D_ + c8);
        }
#pragma unroll
        for (int l = 0; l < 16; l++) {
            int f = tid + l * 128;
            int row = f >> 3, c8 = (f & 7) * 8;
            cpa16(smem_u32 + (VS_OFF(0) + row * 72 + c8) * 2,
                  Vg + (size_t)row * N_ + c8);
        }
        CP_COMMIT();
    }

    float m0r = -INFINITY, m1r = -INFINITY, l0r = 0.f, l1r = 0.f;
    float acc[32][4];
#pragma unroll
    for (int j = 0; j < 32; j++)
#pragma unroll
        for (int i = 0; i < 4; i++) acc[j][i] = 0.f;

    for (int mt = 0; mt < NT; mt++) {
        __syncthreads();   // protect stage being overwritten below
        if (mt + 1 < NT) {
            int s = (mt + 1) & 1, n0g = (mt + 1) * 64;
#pragma unroll
            for (int l = 0; l < 4; l++) {
                int f = tid + l * 128;
                int row = f >> 3, c8 = (f & 7) * 8;
                cpa16(smem_u32 + (KS_OFF(s) + row * 72 + c8) * 2,
                      Kg + (size_t)(n0g + row) * D_ + c8);
            }
#pragma unroll
            for (int l = 0; l < 16; l++) {
                int f = tid + l * 128;
                int row = f >> 3, c8 = (f & 7) * 8;
                cpa16(smem_u32 + (VS_OFF(s) + row * 72 + c8) * 2,
                      Vg + (size_t)row * N_ + n0g + c8);
            }
            CP_COMMIT();
            CP_WAIT(1);
        } else {
            CP_WAIT(0);
        }
        __syncthreads();

        const int s = mt & 1;
        const uint32_t ks = smem_u32 + KS_OFF(s) * 2;
        const uint32_t vs = smem_u32 + VS_OFF(s) * 2;

        // ---- S = Q * K^T : warp tile 16 x 64 ----
        float sc[8][4];
#pragma unroll
        for (int j = 0; j < 8; j++)
#pragma unroll
            for (int i = 0; i < 4; i++) sc[j][i] = 0.f;
#pragma unroll
        for (int kk = 0; kk < 4; kk++) {
            int k0 = kk * 16;
            unsigned a0, a1, a2, a3;
            ldsm4(a0, a1, a2, a3,
                  smem_u32 + ((wm + lm_row) * 72 + k0 + lm_k) * 2);
#pragma unroll
            for (int jj = 0; jj < 4; jj++) {
                unsigned r0, r1, r2, r3;
                ldsm4(r0, r1, r2, r3, ks + ((16 * jj + lm_row) * 72 + k0 + lm_k) * 2);
                mma_f16(sc[2 * jj],     a0, a1, a2, a3, r0, r2);
                mma_f16(sc[2 * jj + 1], a0, a1, a2, a3, r1, r3);
            }
        }

        // ---- online softmax in registers ----
        float mx0 = m0r, mx1 = m1r;
#pragma unroll
        for (int j = 0; j < 8; j++) {
            mx0 = fmaxf(mx0, fmaxf(sc[j][0], sc[j][1]));
            mx1 = fmaxf(mx1, fmaxf(sc[j][2], sc[j][3]));
        }
        mx0 = fmaxf(mx0, __shfl_xor_sync(0xffffffffu, mx0, 1));
        mx0 = fmaxf(mx0, __shfl_xor_sync(0xffffffffu, mx0, 2));
        mx1 = fmaxf(mx1, __shfl_xor_sync(0xffffffffu, mx1, 1));
        mx1 = fmaxf(mx1, __shfl_xor_sync(0xffffffffu, mx1, 2));

        float sum0 = 0.f, sum1 = 0.f;
        unsigned ph0[8], ph1[8];
#pragma unroll
        for (int j = 0; j < 8; j++) {
            float p0 = __expf(sc[j][0] - mx0);
            float p1 = __expf(sc[j][1] - mx0);
            float p2 = __expf(sc[j][2] - mx1);
            float p3 = __expf(sc[j][3] - mx1);
            sum0 += p0 + p1; sum1 += p2 + p3;
            ph0[j] = pack_h2(p0, p1);
            ph1[j] = pack_h2(p2, p3);
        }
        sum0 += __shfl_xor_sync(0xffffffffu, sum0, 1);
        sum0 += __shfl_xor_sync(0xffffffffu, sum0, 2);
        sum1 += __shfl_xor_sync(0xffffffffu, sum1, 1);
        sum1 += __shfl_xor_sync(0xffffffffu, sum1, 2);

        float scl0 = __expf(m0r - mx0);
        float scl1 = __expf(m1r - mx1);
        l0r = l0r * scl0 + sum0;
        l1r = l1r * scl1 + sum1;
        m0r = mx0; m1r = mx1;

#pragma unroll
        for (int j = 0; j < 32; j++) {
            acc[j][0] *= scl0; acc[j][1] *= scl0;
            acc[j][2] *= scl1; acc[j][3] *= scl1;
        }

        // ---- O += P * V : warp tile 16 x 256, P from registers ----
#pragma unroll
        for (int kk = 0; kk < 4; kk++) {
            int k0 = kk * 16;
            unsigned a0 = ph0[2 * kk],     a1 = ph1[2 * kk];
            unsigned a2 = ph0[2 * kk + 1], a3 = ph1[2 * kk + 1];
#pragma unroll
            for (int jj = 0; jj < 16; jj++) {
                unsigned r0, r1, r2, r3;
                ldsm4(r0, r1, r2, r3, vs + ((16 * jj + lm_row) * 72 + k0 + lm_k) * 2);
                mma_f16(acc[2 * jj],     a0, a1, a2, a3, r0, r2);
                mma_f16(acc[2 * jj + 1], a0, a1, a2, a3, r1, r3);
            }
        }
    }

    // ---- epilogue: out = gamma * (O / l) + x ----
    const float ga = gamma_p[0];
    const float inv0 = 1.f / l0r, inv1 = 1.f / l1r;
    size_t base0 = ((size_t)b * N_ + qt * 64 + wm + g) * C_ + cs * CH_;
    size_t base1 = base0 + (size_t)8 * C_;
#pragma unroll
    for (int j = 0; j < 32; j++) {
        int col = 8 * j + 2 * t;
        float2 x0 = *(const float2*)(x + base0 + col);
        float2 x1 = *(const float2*)(x + base1 + col);
        float2 o0, o1;
        o0.x = ga * acc[j][0] * inv0 + x0.x;
        o0.y = ga * acc[j][1] * inv0 + x0.y;
        o1.x = ga * acc[j][2] * inv1 + x1.x;
        o1.y = ga * acc[j][3] * inv1 + x1.y;
        *(float2*)(out + base0 + col) = o0;
        *(float2*)(out + base1 + col) = o1;
    }
#undef KS_OFF
#undef VS_OFF
}

// ---------------------------------------------------------------------------
extern "C" void kernel_launch(void* const* d_in, const int* in_sizes, int n_in,
                              void* d_out, int out_size)
{
    const float* x     = (const float*)d_in[0];
    const float* Wq    = (const float*)d_in[1];
    const float* bq    = (const float*)d_in[2];
    const float* Wk    = (const float*)d_in[3];
    const float* bk    = (const float*)d_in[4];
    const float* Wv    = (const float*)d_in[5];
    const float* bv    = (const float*)d_in[6];
    const float* gamma = (const float*)d_in[7];
    float* out = (float*)d_out;

    __half *xh, *wqh, *wkh, *wvh;
    cudaGetSymbolAddress((void**)&xh,  g_Xh);
    cudaGetSymbolAddress((void**)&wqh, g_Wqh);
    cudaGetSymbolAddress((void**)&wkh, g_Wkh);
    cudaGetSymbolAddress((void**)&wvh, g_Wvh);

    const int nx = B_ * N_ * C_;
    f2h_kernel<<<nx / (256 * 8), 256>>>(x, xh, nx);
    f2h_kernel<<<(D_ * C_) / (256 * 8), 256>>>(Wq, wqh, D_ * C_);
    f2h_kernel<<<(D_ * C_) / (256 * 8), 256>>>(Wk, wkh, D_ * C_);
    f2h_kernel<<<(C_ * C_) / (256 * 8), 256>>>(Wv, wvh, C_ * C_);

    proj_kernel<<<dim3(10, (B_ * N_) / 64), 256>>>(bq, bk, bv);

    const int smem_bytes = (4608 + 2 * 4608 + 2 * 18432) * 2;   // 101376
    cudaFuncSetAttribute(attn_kernel,
                         cudaFuncAttributeMaxDynamicSharedMemorySize, smem_bytes);
    attn_kernel<<<dim3(CS_, N_ / 64, B_), 128, smem_bytes>>>(x, gamma, out);
}